// round 1
// baseline (speedup 1.0000x reference)
#include <cuda_runtime.h>
#include <cstddef>

// Problem constants
#define PB 4
#define PN 16384
#define PM 16384
#define PK 16
#define PC 64
#define PO 64
#define PG 8

static __device__ float g_xv[PB * PN * PO];   // x_v = fea^T @ Wv + bv   [B,N,64] row-contig
static __device__ float g_a [PB * PN * PG];   // (x_k @ we_w1)*we_s + a0 [B,N,8]
static __device__ float g_c [PB * PM * PG];   // ((x_q-cpr)@we_w1)*we_s - we_b  [B,M,8]
static __device__ float g_wka[PC * PG];       // (Wk  @ we_w1) * we_s
static __device__ float g_wqa[PC * PG];       // (Wq  @ we_w1) * we_s
static __device__ float g_wca[PO * PG];       // (cpe_w2 @ we_w1) * we_s
static __device__ float g_c0[PG];             // ((bq - cpe_b2)@we_w1)*we_s - we_b
static __device__ float g_a0[PG];             // (bk @ we_w1) * we_s
static __device__ float g_pw1f[3 * PO];       // pe_w1  col-scaled by pe_s
static __device__ float g_cw1f[3 * PO];       // cpe_w1 col-scaled by cpe_s

// ---------------------------------------------------------------------------
// Kernel 0: fold small weight combos (1 block, 512 threads)
// ---------------------------------------------------------------------------
__global__ void fold_kernel(const float* __restrict__ Wq, const float* __restrict__ bq,
                            const float* __restrict__ Wk, const float* __restrict__ bk,
                            const float* __restrict__ cpe_w1, const float* __restrict__ cpe_s,
                            const float* __restrict__ cpe_w2, const float* __restrict__ cpe_b2,
                            const float* __restrict__ pe_w1, const float* __restrict__ pe_s,
                            const float* __restrict__ we_w1, const float* __restrict__ we_s,
                            const float* __restrict__ we_b) {
    int tid = threadIdx.x;             // 512 threads
    int c = tid >> 3, g = tid & 7;
    float s = we_s[g];
    float aK = 0.f, aQ = 0.f, aC = 0.f;
    #pragma unroll 8
    for (int o = 0; o < 64; o++) {
        float w1 = we_w1[o * 8 + g];
        aK = fmaf(Wk[c * 64 + o],     w1, aK);
        aQ = fmaf(Wq[c * 64 + o],     w1, aQ);
        aC = fmaf(cpe_w2[c * 64 + o], w1, aC);
    }
    g_wka[c * 8 + g] = aK * s;
    g_wqa[c * 8 + g] = aQ * s;
    g_wca[c * 8 + g] = aC * s;

    if (tid < 8) {
        float a0 = 0.f, c0 = 0.f;
        for (int o = 0; o < 64; o++) {
            float w1 = we_w1[o * 8 + tid];
            a0 = fmaf(bk[o], w1, a0);
            c0 = fmaf(bq[o] - cpe_b2[o], w1, c0);
        }
        g_a0[tid] = a0 * we_s[tid];
        g_c0[tid] = c0 * we_s[tid] - we_b[tid];
    }
    if (tid < 192) {
        int j = tid % 64;
        g_pw1f[tid] = pe_w1[tid]  * pe_s[j];
        g_cw1f[tid] = cpe_w1[tid] * cpe_s[j];
    }
}

// ---------------------------------------------------------------------------
// Kernel 1: per-point precompute: x_v (64) and a (8).  256 thr/block, 1 pt/thr.
// ---------------------------------------------------------------------------
__global__ void point_kernel(const float* __restrict__ fea,
                             const float* __restrict__ Wv,
                             const float* __restrict__ bv) {
    __shared__ float sWv[64 * 64];
    __shared__ float sWka[64 * 8];
    __shared__ float sbv[64];
    __shared__ float sa0[8];
    int tid = threadIdx.x;
    for (int i = tid; i < 4096; i += 256) sWv[i] = Wv[i];
    for (int i = tid; i < 512; i += 256)  sWka[i] = g_wka[i];
    if (tid < 64) sbv[tid] = bv[tid];
    if (tid < 8)  sa0[tid] = g_a0[tid];
    __syncthreads();

    int gp = blockIdx.x * 256 + tid;        // global point
    int b = gp >> 14;
    int n = gp & (PN - 1);
    const float* fp = fea + (size_t)b * PC * PN + n;

    float acc[64];
    float ag[8];
    #pragma unroll
    for (int o = 0; o < 64; o++) acc[o] = sbv[o];
    #pragma unroll
    for (int g = 0; g < 8; g++) ag[g] = sa0[g];

    #pragma unroll 4
    for (int c = 0; c < 64; c++) {
        float f = fp[(size_t)c * PN];
        const float4* wr = (const float4*)(sWv + c * 64);
        #pragma unroll
        for (int o4 = 0; o4 < 16; o4++) {
            float4 w = wr[o4];
            acc[o4 * 4 + 0] = fmaf(f, w.x, acc[o4 * 4 + 0]);
            acc[o4 * 4 + 1] = fmaf(f, w.y, acc[o4 * 4 + 1]);
            acc[o4 * 4 + 2] = fmaf(f, w.z, acc[o4 * 4 + 2]);
            acc[o4 * 4 + 3] = fmaf(f, w.w, acc[o4 * 4 + 3]);
        }
        const float4* kr = (const float4*)(sWka + c * 8);
        float4 k0 = kr[0], k1 = kr[1];
        ag[0] = fmaf(f, k0.x, ag[0]); ag[1] = fmaf(f, k0.y, ag[1]);
        ag[2] = fmaf(f, k0.z, ag[2]); ag[3] = fmaf(f, k0.w, ag[3]);
        ag[4] = fmaf(f, k1.x, ag[4]); ag[5] = fmaf(f, k1.y, ag[5]);
        ag[6] = fmaf(f, k1.z, ag[6]); ag[7] = fmaf(f, k1.w, ag[7]);
    }

    float4* ov = (float4*)(g_xv + (size_t)gp * 64);
    #pragma unroll
    for (int o4 = 0; o4 < 16; o4++)
        ov[o4] = make_float4(acc[o4 * 4 + 0], acc[o4 * 4 + 1], acc[o4 * 4 + 2], acc[o4 * 4 + 3]);
    float4* av = (float4*)(g_a + (size_t)gp * 8);
    av[0] = make_float4(ag[0], ag[1], ag[2], ag[3]);
    av[1] = make_float4(ag[4], ag[5], ag[6], ag[7]);
}

// ---------------------------------------------------------------------------
// Kernel 2: per-center precompute: c' = ((x_q - cpr)@we_w1)*s - b   [B,M,8]
// ---------------------------------------------------------------------------
__global__ void center_kernel(const float* __restrict__ center_pos,
                              const float* __restrict__ center_fea,
                              const float* __restrict__ cpe_b) {
    __shared__ float sWqa[512];
    __shared__ float sWca[512];
    __shared__ float sw1[192];
    __shared__ float sb1[64];
    int tid = threadIdx.x;
    for (int i = tid; i < 512; i += 256) { sWqa[i] = g_wqa[i]; sWca[i] = g_wca[i]; }
    if (tid < 192) sw1[tid] = g_cw1f[tid];
    if (tid < 64)  sb1[tid] = cpe_b[tid];
    __syncthreads();

    int gid = blockIdx.x * 256 + tid;
    int b = gid >> 14;
    int m = gid & (PM - 1);
    float px = center_pos[(size_t)gid * 3 + 0];
    float py = center_pos[(size_t)gid * 3 + 1];
    float pz = center_pos[(size_t)gid * 3 + 2];

    float acc[8];
    #pragma unroll
    for (int g = 0; g < 8; g++) acc[g] = __ldg(g_c0 + g);

    const float* cf = center_fea + (size_t)b * PC * PM + m;
    #pragma unroll 4
    for (int i = 0; i < 64; i++) {
        float h = fmaxf(fmaf(px, sw1[i], fmaf(py, sw1[64 + i], fmaf(pz, sw1[128 + i], sb1[i]))), 0.f);
        float f = cf[(size_t)i * PM];
        const float4* qa = (const float4*)(sWqa + i * 8);
        const float4* ca = (const float4*)(sWca + i * 8);
        float4 q0 = qa[0], q1 = qa[1], c0 = ca[0], c1 = ca[1];
        acc[0] += f * q0.x - h * c0.x;  acc[1] += f * q0.y - h * c0.y;
        acc[2] += f * q0.z - h * c0.z;  acc[3] += f * q0.w - h * c0.w;
        acc[4] += f * q1.x - h * c1.x;  acc[5] += f * q1.y - h * c1.y;
        acc[6] += f * q1.z - h * c1.z;  acc[7] += f * q1.w - h * c1.w;
    }
    float4* cv = (float4*)(g_c + (size_t)gid * 8);
    cv[0] = make_float4(acc[0], acc[1], acc[2], acc[3]);
    cv[1] = make_float4(acc[4], acc[5], acc[6], acc[7]);
}

// ---------------------------------------------------------------------------
// Kernel 3: main attention. 128 thr/block = 16 centers x 8 threads.
// Thread t of a center owns j-slice [t*8, t*8+8) of the hidden dim and
// output slice o = t*8 + i (group g == t).
// ---------------------------------------------------------------------------
__global__ void attn_kernel(const float* __restrict__ center_pos,
                            const float* __restrict__ pos,
                            const int* __restrict__ idx,
                            const float* __restrict__ pe_w2,
                            const float* __restrict__ pe_b,
                            const float* __restrict__ pe_b2,
                            const float* __restrict__ we_w2,
                            const float* __restrict__ we_b2,
                            float* __restrict__ out) {
    extern __shared__ float sm[];
    float* s_pw2  = sm;              // 4096 floats: pe_w2 [j][o]
    float* s_we2  = sm + 4096;       // 64
    float* s_web2 = sm + 4160;       // 8
    float* s_H    = sm + 4168;       // 16 centers * 520 (8 rows, stride 65)
    float* s_out  = s_H;             // overlay: 64 * 17

    const int tid = threadIdx.x;
    for (int i = tid; i < 4096; i += 128) s_pw2[i] = pe_w2[i];
    if (tid < 64) s_we2[tid] = we_w2[tid];
    if (tid < 8)  s_web2[tid] = we_b2[tid];
    __syncthreads();

    const unsigned FULL = 0xffffffffu;
    const int grp = tid >> 3;
    const int t = tid & 7;
    const int gidBase = blockIdx.x * 16;
    const int gid = gidBase + grp;
    const int b = gid >> 14;
    const int m0 = gidBase & (PM - 1);

    // --- indices for my two edges ---
    int2 i01 = ((const int2*)(idx + (size_t)gid * 16))[t];
    int i0 = i01.x, i1 = i01.y;

    // --- c' for this center ---
    const float4* cpv = (const float4*)(g_c + (size_t)gid * 8);
    float4 cA = cpv[0], cB = cpv[1];
    float cpr8[8] = {cA.x, cA.y, cA.z, cA.w, cB.x, cB.y, cB.z, cB.w};

    // --- logits for my two edges ---
    float lg0[8], lg1[8];
    #pragma unroll
    for (int e = 0; e < 2; e++) {
        int ik = e ? i1 : i0;
        const float4* ap = (const float4*)(g_a + ((size_t)b * PN + ik) * 8);
        float4 a0 = ap[0], a1 = ap[1];
        float h1[8];
        h1[0] = fmaxf(a0.x - cpr8[0], 0.f); h1[1] = fmaxf(a0.y - cpr8[1], 0.f);
        h1[2] = fmaxf(a0.z - cpr8[2], 0.f); h1[3] = fmaxf(a0.w - cpr8[3], 0.f);
        h1[4] = fmaxf(a1.x - cpr8[4], 0.f); h1[5] = fmaxf(a1.y - cpr8[5], 0.f);
        h1[6] = fmaxf(a1.z - cpr8[6], 0.f); h1[7] = fmaxf(a1.w - cpr8[7], 0.f);
        float* lg = e ? lg1 : lg0;
        #pragma unroll
        for (int g = 0; g < 8; g++) {
            float acc = s_web2[g];
            #pragma unroll
            for (int gp = 0; gp < 8; gp++)
                acc = fmaf(h1[gp], s_we2[gp * 8 + g], acc);
            lg[g] = acc;
        }
    }

    // --- softmax over 16 k (2 per lane across 8 lanes) ---
    float mx[8];
    #pragma unroll
    for (int g = 0; g < 8; g++) mx[g] = fmaxf(lg0[g], lg1[g]);
    #pragma unroll
    for (int s = 1; s < 8; s <<= 1)
        #pragma unroll
        for (int g = 0; g < 8; g++)
            mx[g] = fmaxf(mx[g], __shfl_xor_sync(FULL, mx[g], s, 8));
    float w0[8], w1[8], sum[8];
    #pragma unroll
    for (int g = 0; g < 8; g++) {
        w0[g] = __expf(lg0[g] - mx[g]);
        w1[g] = __expf(lg1[g] - mx[g]);
        sum[g] = w0[g] + w1[g];
    }
    #pragma unroll
    for (int s = 1; s < 8; s <<= 1)
        #pragma unroll
        for (int g = 0; g < 8; g++)
            sum[g] += __shfl_xor_sync(FULL, sum[g], s, 8);
    #pragma unroll
    for (int g = 0; g < 8; g++) {
        float inv = __fdividef(1.f, sum[g]);
        w0[g] *= inv;
        w1[g] *= inv;
    }

    // --- per-thread pe_w1 slice (folded with pe_s) + bias ---
    float wxa[8], wxb[8], wxc[8], bb[8];
    #pragma unroll
    for (int jj = 0; jj < 8; jj++) {
        wxa[jj] = __ldg(g_pw1f + 0 * 64 + t * 8 + jj);
        wxb[jj] = __ldg(g_pw1f + 1 * 64 + t * 8 + jj);
        wxc[jj] = __ldg(g_pw1f + 2 * 64 + t * 8 + jj);
        bb[jj]  = __ldg(pe_b + t * 8 + jj);
    }
    float cx = center_pos[(size_t)gid * 3 + 0];
    float cy = center_pos[(size_t)gid * 3 + 1];
    float cz = center_pos[(size_t)gid * 3 + 2];

    // --- edge loop: accumulate H[g][j-slice] and weighted nv ---
    float Hc[64];
    float onv[8];
    #pragma unroll
    for (int i = 0; i < 64; i++) Hc[i] = 0.f;
    #pragma unroll
    for (int i = 0; i < 8; i++) onv[i] = 0.f;

    #pragma unroll
    for (int k = 0; k < 16; k++) {
        const int src = k >> 1;
        int ik = __shfl_sync(FULL, (k & 1) ? i1 : i0, src, 8);

        const float* pp = pos + ((size_t)b * PN + ik) * 3;
        float dx = pp[0] - cx, dy = pp[1] - cy, dz = pp[2] - cz;

        float h[8];
        #pragma unroll
        for (int jj = 0; jj < 8; jj++)
            h[jj] = fmaxf(fmaf(dx, wxa[jj], fmaf(dy, wxb[jj], fmaf(dz, wxc[jj], bb[jj]))), 0.f);

        const float4* vp = (const float4*)(g_xv + ((size_t)b * PN + ik) * 64 + t * 8);
        float4 v0 = vp[0], v1 = vp[1];

        float wt = 0.f;
        #pragma unroll
        for (int g = 0; g < 8; g++) {
            float wg = __shfl_sync(FULL, (k & 1) ? w1[g] : w0[g], src, 8);
            #pragma unroll
            for (int jj = 0; jj < 8; jj++)
                Hc[g * 8 + jj] = fmaf(wg, h[jj], Hc[g * 8 + jj]);
            if (g == t) wt = wg;   // predicated select, no dynamic reg index
        }
        onv[0] = fmaf(wt, v0.x, onv[0]); onv[1] = fmaf(wt, v0.y, onv[1]);
        onv[2] = fmaf(wt, v0.z, onv[2]); onv[3] = fmaf(wt, v0.w, onv[3]);
        onv[4] = fmaf(wt, v1.x, onv[4]); onv[5] = fmaf(wt, v1.y, onv[5]);
        onv[6] = fmaf(wt, v1.z, onv[6]); onv[7] = fmaf(wt, v1.w, onv[7]);
    }

    // --- H transpose through shared (stride 65: conflict-free reads) ---
    {
        float* hb = s_H + grp * 520 + t * 8;
        #pragma unroll
        for (int g = 0; g < 8; g++)
            #pragma unroll
            for (int jj = 0; jj < 8; jj++)
                hb[g * 65 + jj] = Hc[g * 8 + jj];
    }
    __syncthreads();

    // --- final contraction: out[o=t*8+i] = onv[i] + pe_b2[o] + H[t]·pe_w2[:,o] ---
    float pr[8];
    #pragma unroll
    for (int i = 0; i < 8; i++) pr[i] = __ldg(pe_b2 + t * 8 + i);
    const float* hrow = s_H + grp * 520 + t * 65;
    #pragma unroll 8
    for (int j = 0; j < 64; j++) {
        float hv = hrow[j];
        const float4* wr = (const float4*)(s_pw2 + j * 64 + t * 8);
        float4 p0 = wr[0], p1 = wr[1];
        pr[0] = fmaf(hv, p0.x, pr[0]); pr[1] = fmaf(hv, p0.y, pr[1]);
        pr[2] = fmaf(hv, p0.z, pr[2]); pr[3] = fmaf(hv, p0.w, pr[3]);
        pr[4] = fmaf(hv, p1.x, pr[4]); pr[5] = fmaf(hv, p1.y, pr[5]);
        pr[6] = fmaf(hv, p1.z, pr[6]); pr[7] = fmaf(hv, p1.w, pr[7]);
    }
    __syncthreads();

    // --- stage output [o][m_local] for coalesced [B,O,M] writes ---
    #pragma unroll
    for (int i = 0; i < 8; i++)
        s_out[(t * 8 + i) * 17 + grp] = onv[i] + pr[i];
    __syncthreads();

    float* ob = out + (size_t)b * PO * PM + m0;
    #pragma unroll
    for (int q = 0; q < 8; q++) {
        int lin = q * 128 + tid;
        int o = lin >> 4;
        int ml = lin & 15;
        ob[(size_t)o * PM + ml] = s_out[o * 17 + ml];
    }
}

// ---------------------------------------------------------------------------
extern "C" void kernel_launch(void* const* d_in, const int* in_sizes, int n_in,
                              void* d_out, int out_size) {
    (void)in_sizes; (void)n_in; (void)out_size;
    const float* center_pos = (const float*)d_in[0];
    const float* center_fea = (const float*)d_in[1];
    const float* pos        = (const float*)d_in[2];
    const float* fea        = (const float*)d_in[3];
    const int*   idx        = (const int*)d_in[4];
    const float* Wq  = (const float*)d_in[5];
    const float* bq  = (const float*)d_in[6];
    const float* Wk  = (const float*)d_in[7];
    const float* bk  = (const float*)d_in[8];
    const float* Wv  = (const float*)d_in[9];
    const float* bv  = (const float*)d_in[10];
    const float* cpe_w1 = (const float*)d_in[11];
    const float* cpe_s  = (const float*)d_in[12];
    const float* cpe_b  = (const float*)d_in[13];
    const float* cpe_w2 = (const float*)d_in[14];
    const float* cpe_b2 = (const float*)d_in[15];
    const float* pe_w1  = (const float*)d_in[16];
    const float* pe_s   = (const float*)d_in[17];
    const float* pe_b   = (const float*)d_in[18];
    const float* pe_w2  = (const float*)d_in[19];
    const float* pe_b2  = (const float*)d_in[20];
    const float* we_w1  = (const float*)d_in[21];
    const float* we_s   = (const float*)d_in[22];
    const float* we_b   = (const float*)d_in[23];
    const float* we_w2  = (const float*)d_in[24];
    const float* we_b2  = (const float*)d_in[25];
    float* out = (float*)d_out;

    fold_kernel<<<1, 512>>>(Wq, bq, Wk, bk, cpe_w1, cpe_s, cpe_w2, cpe_b2,
                            pe_w1, pe_s, we_w1, we_s, we_b);
    point_kernel<<<(PB * PN) / 256, 256>>>(fea, Wv, bv);
    center_kernel<<<(PB * PM) / 256, 256>>>(center_pos, center_fea, cpe_b);

    const int smem = (4096 + 64 + 8 + 16 * 520) * 4;  // 49,952 bytes
    cudaFuncSetAttribute(attn_kernel, cudaFuncAttributeMaxDynamicSharedMemorySize, smem);
    attn_kernel<<<(PB * PM) / 16, 128, smem>>>(center_pos, pos, idx,
                                               pe_w2, pe_b, pe_b2, we_w2, we_b2, out);
}

// round 2
// speedup vs baseline: 1.2926x; 1.2926x over previous
#include <cuda_runtime.h>
#include <cstddef>

// Problem constants
#define PB 4
#define PN 16384
#define PM 16384
#define PK 16
#define PC 64
#define PO 64
#define PG 8

static __device__ float g_xv[PB * PN * PO];   // x_v = fea^T @ Wv + bv   [B,N,64] row-contig
static __device__ float g_a [PB * PN * PG];   // (x_k @ we_w1)*we_s + a0 [B,N,8]
static __device__ float g_c [PB * PM * PG];   // ((x_q-cpr)@we_w1)*we_s - we_b  [B,M,8]
static __device__ float g_wka[PC * PG];       // (Wk  @ we_w1) * we_s
static __device__ float g_wqa[PC * PG];       // (Wq  @ we_w1) * we_s
static __device__ float g_wca[PO * PG];       // (cpe_w2 @ we_w1) * we_s
static __device__ float g_c0[PG];             // ((bq - cpe_b2)@we_w1)*we_s - we_b
static __device__ float g_a0[PG];             // (bk @ we_w1) * we_s
static __device__ float g_pw1f[3 * PO];       // pe_w1  col-scaled by pe_s
static __device__ float g_cw1f[3 * PO];       // cpe_w1 col-scaled by cpe_s

// ---------------------------------------------------------------------------
// Kernel 0: fold small weight combos (1 block, 512 threads)
// ---------------------------------------------------------------------------
__global__ void fold_kernel(const float* __restrict__ Wq, const float* __restrict__ bq,
                            const float* __restrict__ Wk, const float* __restrict__ bk,
                            const float* __restrict__ cpe_w1, const float* __restrict__ cpe_s,
                            const float* __restrict__ cpe_w2, const float* __restrict__ cpe_b2,
                            const float* __restrict__ pe_w1, const float* __restrict__ pe_s,
                            const float* __restrict__ we_w1, const float* __restrict__ we_s,
                            const float* __restrict__ we_b) {
    int tid = threadIdx.x;             // 512 threads
    int c = tid >> 3, g = tid & 7;
    float s = we_s[g];
    float aK = 0.f, aQ = 0.f, aC = 0.f;
    #pragma unroll 8
    for (int o = 0; o < 64; o++) {
        float w1 = we_w1[o * 8 + g];
        aK = fmaf(Wk[c * 64 + o],     w1, aK);
        aQ = fmaf(Wq[c * 64 + o],     w1, aQ);
        aC = fmaf(cpe_w2[c * 64 + o], w1, aC);
    }
    g_wka[c * 8 + g] = aK * s;
    g_wqa[c * 8 + g] = aQ * s;
    g_wca[c * 8 + g] = aC * s;

    if (tid < 8) {
        float a0 = 0.f, c0 = 0.f;
        for (int o = 0; o < 64; o++) {
            float w1 = we_w1[o * 8 + tid];
            a0 = fmaf(bk[o], w1, a0);
            c0 = fmaf(bq[o] - cpe_b2[o], w1, c0);
        }
        g_a0[tid] = a0 * we_s[tid];
        g_c0[tid] = c0 * we_s[tid] - we_b[tid];
    }
    if (tid < 192) {
        int j = tid % 64;
        g_pw1f[tid] = pe_w1[tid]  * pe_s[j];
        g_cw1f[tid] = cpe_w1[tid] * cpe_s[j];
    }
}

// ---------------------------------------------------------------------------
// Kernel 1: per-point precompute: x_v (64) and a (8).  256 thr/block, 1 pt/thr.
// ---------------------------------------------------------------------------
__global__ void point_kernel(const float* __restrict__ fea,
                             const float* __restrict__ Wv,
                             const float* __restrict__ bv) {
    __shared__ float sWv[64 * 64];
    __shared__ float sWka[64 * 8];
    __shared__ float sbv[64];
    __shared__ float sa0[8];
    int tid = threadIdx.x;
    for (int i = tid; i < 4096; i += 256) sWv[i] = Wv[i];
    for (int i = tid; i < 512; i += 256)  sWka[i] = g_wka[i];
    if (tid < 64) sbv[tid] = bv[tid];
    if (tid < 8)  sa0[tid] = g_a0[tid];
    __syncthreads();

    int gp = blockIdx.x * 256 + tid;        // global point
    int b = gp >> 14;
    int n = gp & (PN - 1);
    const float* fp = fea + (size_t)b * PC * PN + n;

    float acc[64];
    float ag[8];
    #pragma unroll
    for (int o = 0; o < 64; o++) acc[o] = sbv[o];
    #pragma unroll
    for (int g = 0; g < 8; g++) ag[g] = sa0[g];

    #pragma unroll 4
    for (int c = 0; c < 64; c++) {
        float f = fp[(size_t)c * PN];
        const float4* wr = (const float4*)(sWv + c * 64);
        #pragma unroll
        for (int o4 = 0; o4 < 16; o4++) {
            float4 w = wr[o4];
            acc[o4 * 4 + 0] = fmaf(f, w.x, acc[o4 * 4 + 0]);
            acc[o4 * 4 + 1] = fmaf(f, w.y, acc[o4 * 4 + 1]);
            acc[o4 * 4 + 2] = fmaf(f, w.z, acc[o4 * 4 + 2]);
            acc[o4 * 4 + 3] = fmaf(f, w.w, acc[o4 * 4 + 3]);
        }
        const float4* kr = (const float4*)(sWka + c * 8);
        float4 k0 = kr[0], k1 = kr[1];
        ag[0] = fmaf(f, k0.x, ag[0]); ag[1] = fmaf(f, k0.y, ag[1]);
        ag[2] = fmaf(f, k0.z, ag[2]); ag[3] = fmaf(f, k0.w, ag[3]);
        ag[4] = fmaf(f, k1.x, ag[4]); ag[5] = fmaf(f, k1.y, ag[5]);
        ag[6] = fmaf(f, k1.z, ag[6]); ag[7] = fmaf(f, k1.w, ag[7]);
    }

    float4* ov = (float4*)(g_xv + (size_t)gp * 64);
    #pragma unroll
    for (int o4 = 0; o4 < 16; o4++)
        ov[o4] = make_float4(acc[o4 * 4 + 0], acc[o4 * 4 + 1], acc[o4 * 4 + 2], acc[o4 * 4 + 3]);
    float4* av = (float4*)(g_a + (size_t)gp * 8);
    av[0] = make_float4(ag[0], ag[1], ag[2], ag[3]);
    av[1] = make_float4(ag[4], ag[5], ag[6], ag[7]);
}

// ---------------------------------------------------------------------------
// Kernel 2: per-center precompute: c' = ((x_q - cpr)@we_w1)*s - b   [B,M,8]
// ---------------------------------------------------------------------------
__global__ void center_kernel(const float* __restrict__ center_pos,
                              const float* __restrict__ center_fea,
                              const float* __restrict__ cpe_b) {
    __shared__ float sWqa[512];
    __shared__ float sWca[512];
    __shared__ float sw1[192];
    __shared__ float sb1[64];
    int tid = threadIdx.x;
    for (int i = tid; i < 512; i += 256) { sWqa[i] = g_wqa[i]; sWca[i] = g_wca[i]; }
    if (tid < 192) sw1[tid] = g_cw1f[tid];
    if (tid < 64)  sb1[tid] = cpe_b[tid];
    __syncthreads();

    int gid = blockIdx.x * 256 + tid;
    int b = gid >> 14;
    int m = gid & (PM - 1);
    float px = center_pos[(size_t)gid * 3 + 0];
    float py = center_pos[(size_t)gid * 3 + 1];
    float pz = center_pos[(size_t)gid * 3 + 2];

    float acc[8];
    #pragma unroll
    for (int g = 0; g < 8; g++) acc[g] = __ldg(g_c0 + g);

    const float* cf = center_fea + (size_t)b * PC * PM + m;
    #pragma unroll 4
    for (int i = 0; i < 64; i++) {
        float h = fmaxf(fmaf(px, sw1[i], fmaf(py, sw1[64 + i], fmaf(pz, sw1[128 + i], sb1[i]))), 0.f);
        float f = cf[(size_t)i * PM];
        const float4* qa = (const float4*)(sWqa + i * 8);
        const float4* ca = (const float4*)(sWca + i * 8);
        float4 q0 = qa[0], q1 = qa[1], c0 = ca[0], c1 = ca[1];
        acc[0] += f * q0.x - h * c0.x;  acc[1] += f * q0.y - h * c0.y;
        acc[2] += f * q0.z - h * c0.z;  acc[3] += f * q0.w - h * c0.w;
        acc[4] += f * q1.x - h * c1.x;  acc[5] += f * q1.y - h * c1.y;
        acc[6] += f * q1.z - h * c1.z;  acc[7] += f * q1.w - h * c1.w;
    }
    float4* cv = (float4*)(g_c + (size_t)gid * 8);
    cv[0] = make_float4(acc[0], acc[1], acc[2], acc[3]);
    cv[1] = make_float4(acc[4], acc[5], acc[6], acc[7]);
}

// ---------------------------------------------------------------------------
// Kernel 3: main attention. 256 thr/block = 16 centers x 16 threads.
// Thread t of a center owns j-slice [t*4, t*4+4) and outputs o = t*4..t*4+3
// (group g = t>>1). Per-center state (idx, rel-pos, softmax w) staged in smem
// by the prologue (1 edge per lane), consumed via broadcast LDS in the loop.
// ---------------------------------------------------------------------------
// smem float layout:
//   0      s_pw2  [4096]
//   4096   s_we2  [64]
//   4160   s_web2 [16]   (8 used, padded for alignment)
//   4176   s_ik   [256]  (int)
//   4432   s_d    [256*4]  float4 per (ci,k)
//   5456   s_w    [512*4]  2 x float4 per (ci,k)
//   7504   s_H    [16*544]  per center: 8 rows x 68 (float4-aligned rows)
//   (s_out [64*17] overlays s_H after a __syncthreads)
#define SM_WE2   4096
#define SM_WEB2  4160
#define SM_IK    4176
#define SM_D     4432
#define SM_W     5456
#define SM_H     7504
#define SM_TOT   (7504 + 16 * 544)

__global__ void __launch_bounds__(256, 2)
attn_kernel(const float* __restrict__ center_pos,
            const float* __restrict__ pos,
            const int* __restrict__ idx,
            const float* __restrict__ pe_w2,
            const float* __restrict__ pe_b,
            const float* __restrict__ pe_b2,
            const float* __restrict__ we_w2,
            const float* __restrict__ we_b2,
            float* __restrict__ out) {
    extern __shared__ float sm[];
    float*  s_pw2 = sm;
    float*  s_we2 = sm + SM_WE2;
    float*  s_web2= sm + SM_WEB2;
    int*    s_ik  = (int*)(sm + SM_IK);
    float4* s_d   = (float4*)(sm + SM_D);
    float4* s_w4  = (float4*)(sm + SM_W);
    float*  s_wf  = sm + SM_W;
    float*  s_H   = sm + SM_H;

    const int tid = threadIdx.x;
    for (int i = tid; i < 4096; i += 256) s_pw2[i] = pe_w2[i];
    if (tid < 64) s_we2[tid] = we_w2[tid];
    if (tid < 8)  s_web2[tid] = we_b2[tid];
    __syncthreads();

    const unsigned FULL = 0xffffffffu;
    const int ci = tid >> 4;           // center within block
    const int t  = tid & 15;           // lane within center
    const int g  = t >> 1;             // my output group
    const int gidBase = blockIdx.x * 16;
    const int gid = gidBase + ci;
    const int b = gid >> 14;

    // --- prologue: my edge (k = t) ---
    int myik;
    {
        int ik = idx[(size_t)gid * 16 + t];
        myik = b * PN + ik;
        s_ik[ci * 16 + t] = myik;
        const float* pp = pos + (size_t)myik * 3;
        float cx = center_pos[(size_t)gid * 3 + 0];
        float cy = center_pos[(size_t)gid * 3 + 1];
        float cz = center_pos[(size_t)gid * 3 + 2];
        s_d[ci * 16 + t] = make_float4(pp[0] - cx, pp[1] - cy, pp[2] - cz, 0.f);
    }

    // --- logits for my edge ---
    {
        const float4* cpv = (const float4*)(g_c + (size_t)gid * 8);
        float4 cA = cpv[0], cB = cpv[1];
        const float4* ap = (const float4*)(g_a + (size_t)myik * 8);
        float4 a0 = ap[0], a1 = ap[1];
        float h1[8];
        h1[0] = fmaxf(a0.x - cA.x, 0.f); h1[1] = fmaxf(a0.y - cA.y, 0.f);
        h1[2] = fmaxf(a0.z - cA.z, 0.f); h1[3] = fmaxf(a0.w - cA.w, 0.f);
        h1[4] = fmaxf(a1.x - cB.x, 0.f); h1[5] = fmaxf(a1.y - cB.y, 0.f);
        h1[6] = fmaxf(a1.z - cB.z, 0.f); h1[7] = fmaxf(a1.w - cB.w, 0.f);
        float lg[8];
        #pragma unroll
        for (int gg = 0; gg < 8; gg++) {
            float acc = s_web2[gg];
            #pragma unroll
            for (int gp = 0; gp < 8; gp++)
                acc = fmaf(h1[gp], s_we2[gp * 8 + gg], acc);
            lg[gg] = acc;
        }
        // softmax over 16 lanes (edges)
        float mx[8];
        #pragma unroll
        for (int gg = 0; gg < 8; gg++) mx[gg] = lg[gg];
        #pragma unroll
        for (int s = 1; s < 16; s <<= 1)
            #pragma unroll
            for (int gg = 0; gg < 8; gg++)
                mx[gg] = fmaxf(mx[gg], __shfl_xor_sync(FULL, mx[gg], s, 16));
        float e[8], sum[8];
        #pragma unroll
        for (int gg = 0; gg < 8; gg++) { e[gg] = __expf(lg[gg] - mx[gg]); sum[gg] = e[gg]; }
        #pragma unroll
        for (int s = 1; s < 16; s <<= 1)
            #pragma unroll
            for (int gg = 0; gg < 8; gg++)
                sum[gg] += __shfl_xor_sync(FULL, sum[gg], s, 16);
        #pragma unroll
        for (int gg = 0; gg < 8; gg++)
            e[gg] *= __fdividef(1.f, sum[gg]);
        s_w4[(ci * 16 + t) * 2 + 0] = make_float4(e[0], e[1], e[2], e[3]);
        s_w4[(ci * 16 + t) * 2 + 1] = make_float4(e[4], e[5], e[6], e[7]);
    }
    __syncwarp();

    // --- per-thread pe_w1 slice (folded with pe_s) + bias ---
    float wxa[4], wxb[4], wxc[4], bb[4];
    #pragma unroll
    for (int jj = 0; jj < 4; jj++) {
        wxa[jj] = __ldg(g_pw1f + 0 * 64 + t * 4 + jj);
        wxb[jj] = __ldg(g_pw1f + 1 * 64 + t * 4 + jj);
        wxc[jj] = __ldg(g_pw1f + 2 * 64 + t * 4 + jj);
        bb[jj]  = __ldg(pe_b + t * 4 + jj);
    }

    // --- edge loop ---
    float Hc[32];
    float onv[4] = {0.f, 0.f, 0.f, 0.f};
    #pragma unroll
    for (int i = 0; i < 32; i++) Hc[i] = 0.f;

    const float4* xv4 = (const float4*)g_xv;
    #pragma unroll
    for (int k = 0; k < 16; k++) {
        const int ek = ci * 16 + k;
        int ikk = s_ik[ek];
        float4 d  = s_d[ek];
        float4 wA = s_w4[ek * 2 + 0];
        float4 wB = s_w4[ek * 2 + 1];
        float  wt = s_wf[ek * 8 + g];
        float4 v  = xv4[(size_t)ikk * 16 + t];

        #pragma unroll
        for (int jj = 0; jj < 4; jj++) {
            float h = fmaxf(fmaf(d.x, wxa[jj], fmaf(d.y, wxb[jj], fmaf(d.z, wxc[jj], bb[jj]))), 0.f);
            Hc[0 * 4 + jj] = fmaf(wA.x, h, Hc[0 * 4 + jj]);
            Hc[1 * 4 + jj] = fmaf(wA.y, h, Hc[1 * 4 + jj]);
            Hc[2 * 4 + jj] = fmaf(wA.z, h, Hc[2 * 4 + jj]);
            Hc[3 * 4 + jj] = fmaf(wA.w, h, Hc[3 * 4 + jj]);
            Hc[4 * 4 + jj] = fmaf(wB.x, h, Hc[4 * 4 + jj]);
            Hc[5 * 4 + jj] = fmaf(wB.y, h, Hc[5 * 4 + jj]);
            Hc[6 * 4 + jj] = fmaf(wB.z, h, Hc[6 * 4 + jj]);
            Hc[7 * 4 + jj] = fmaf(wB.w, h, Hc[7 * 4 + jj]);
        }
        onv[0] = fmaf(wt, v.x, onv[0]);
        onv[1] = fmaf(wt, v.y, onv[1]);
        onv[2] = fmaf(wt, v.z, onv[2]);
        onv[3] = fmaf(wt, v.w, onv[3]);
    }

    // --- H transpose through smem (warp-local) ---
    {
        float* hb = s_H + ci * 544 + t * 4;
        #pragma unroll
        for (int gg = 0; gg < 8; gg++)
            *(float4*)(hb + gg * 68) = make_float4(Hc[gg * 4 + 0], Hc[gg * 4 + 1],
                                                   Hc[gg * 4 + 2], Hc[gg * 4 + 3]);
    }
    __syncwarp();

    // --- final contraction: pr[i] = pe_b2[o] + sum_j H[g][j] * pe_w2[j][o] ---
    float pr[4];
    #pragma unroll
    for (int i = 0; i < 4; i++) pr[i] = __ldg(pe_b2 + t * 4 + i);
    const float4* hr = (const float4*)(s_H + ci * 544 + g * 68);
    #pragma unroll
    for (int j4 = 0; j4 < 16; j4++) {
        float4 hv = hr[j4];
        const float4* w0 = (const float4*)(s_pw2 + (j4 * 4 + 0) * 64 + t * 4);
        const float4* w1 = (const float4*)(s_pw2 + (j4 * 4 + 1) * 64 + t * 4);
        const float4* w2 = (const float4*)(s_pw2 + (j4 * 4 + 2) * 64 + t * 4);
        const float4* w3 = (const float4*)(s_pw2 + (j4 * 4 + 3) * 64 + t * 4);
        float4 p0 = *w0, p1 = *w1, p2 = *w2, p3 = *w3;
        pr[0] = fmaf(hv.x, p0.x, pr[0]); pr[1] = fmaf(hv.x, p0.y, pr[1]);
        pr[2] = fmaf(hv.x, p0.z, pr[2]); pr[3] = fmaf(hv.x, p0.w, pr[3]);
        pr[0] = fmaf(hv.y, p1.x, pr[0]); pr[1] = fmaf(hv.y, p1.y, pr[1]);
        pr[2] = fmaf(hv.y, p1.z, pr[2]); pr[3] = fmaf(hv.y, p1.w, pr[3]);
        pr[0] = fmaf(hv.z, p2.x, pr[0]); pr[1] = fmaf(hv.z, p2.y, pr[1]);
        pr[2] = fmaf(hv.z, p2.z, pr[2]); pr[3] = fmaf(hv.z, p2.w, pr[3]);
        pr[0] = fmaf(hv.w, p3.x, pr[0]); pr[1] = fmaf(hv.w, p3.y, pr[1]);
        pr[2] = fmaf(hv.w, p3.z, pr[2]); pr[3] = fmaf(hv.w, p3.w, pr[3]);
    }
    __syncthreads();   // everyone done with s_H / s_w — safe to overlay s_out

    // --- stage output [o][m_local] for coalesced [B,O,M] writes ---
    float* s_out = s_H;   // 64 x 17 overlay
    #pragma unroll
    for (int i = 0; i < 4; i++)
        s_out[(t * 4 + i) * 17 + ci] = onv[i] + pr[i];
    __syncthreads();

    const int m0 = gidBase & (PM - 1);
    float* ob = out + (size_t)(gidBase >> 14) * PO * PM + m0;
    #pragma unroll
    for (int q = 0; q < 4; q++) {
        int lin = q * 256 + tid;
        int o = lin >> 4;
        int ml = lin & 15;
        ob[(size_t)o * PM + ml] = s_out[o * 17 + ml];
    }
}

// ---------------------------------------------------------------------------
extern "C" void kernel_launch(void* const* d_in, const int* in_sizes, int n_in,
                              void* d_out, int out_size) {
    (void)in_sizes; (void)n_in; (void)out_size;
    const float* center_pos = (const float*)d_in[0];
    const float* center_fea = (const float*)d_in[1];
    const float* pos        = (const float*)d_in[2];
    const float* fea        = (const float*)d_in[3];
    const int*   idx        = (const int*)d_in[4];
    const float* Wq  = (const float*)d_in[5];
    const float* bq  = (const float*)d_in[6];
    const float* Wk  = (const float*)d_in[7];
    const float* bk  = (const float*)d_in[8];
    const float* Wv  = (const float*)d_in[9];
    const float* bv  = (const float*)d_in[10];
    const float* cpe_w1 = (const float*)d_in[11];
    const float* cpe_s  = (const float*)d_in[12];
    const float* cpe_b  = (const float*)d_in[13];
    const float* cpe_w2 = (const float*)d_in[14];
    const float* cpe_b2 = (const float*)d_in[15];
    const float* pe_w1  = (const float*)d_in[16];
    const float* pe_s   = (const float*)d_in[17];
    const float* pe_b   = (const float*)d_in[18];
    const float* pe_w2  = (const float*)d_in[19];
    const float* pe_b2  = (const float*)d_in[20];
    const float* we_w1  = (const float*)d_in[21];
    const float* we_s   = (const float*)d_in[22];
    const float* we_b   = (const float*)d_in[23];
    const float* we_w2  = (const float*)d_in[24];
    const float* we_b2  = (const float*)d_in[25];
    float* out = (float*)d_out;

    fold_kernel<<<1, 512>>>(Wq, bq, Wk, bk, cpe_w1, cpe_s, cpe_w2, cpe_b2,
                            pe_w1, pe_s, we_w1, we_s, we_b);
    point_kernel<<<(PB * PN) / 256, 256>>>(fea, Wv, bv);
    center_kernel<<<(PB * PM) / 256, 256>>>(center_pos, center_fea, cpe_b);

    const int smem = SM_TOT * 4;   // ~64.8 KB
    cudaFuncSetAttribute(attn_kernel, cudaFuncAttributeMaxDynamicSharedMemorySize, smem);
    attn_kernel<<<(PB * PM) / 16, 256, smem>>>(center_pos, pos, idx,
                                               pe_w2, pe_b, pe_b2, we_w2, we_b2, out);
}

// round 3
// speedup vs baseline: 1.5179x; 1.1743x over previous
#include <cuda_runtime.h>
#include <cstddef>
#include <cstdint>

// Problem constants
#define PB 4
#define PN 16384
#define PM 16384
#define PK 16
#define PC 64
#define PO 64
#define PG 8

typedef unsigned long long ull;

// ---- f32x2 packed helpers (sm_103a FFMA2 path) ----
__device__ __forceinline__ void ffma2(ull& d, ull a, ull b, ull c) {
    asm("fma.rn.f32x2 %0, %1, %2, %3;" : "=l"(d) : "l"(a), "l"(b), "l"(c));
}
__device__ __forceinline__ ull pack2(float lo, float hi) {
    ull r; asm("mov.b64 %0, {%1, %2};" : "=l"(r) : "f"(lo), "f"(hi)); return r;
}
__device__ __forceinline__ float2 unpack2(ull v) {
    float2 f; asm("mov.b64 {%0, %1}, %2;" : "=f"(f.x), "=f"(f.y) : "l"(v)); return f;
}
__device__ __forceinline__ ull lds64(uint32_t a) {
    ull r; asm volatile("ld.shared.b64 %0, [%1];" : "=l"(r) : "r"(a)); return r;
}
__device__ __forceinline__ void lds128(ull& x, ull& y, uint32_t a) {
    asm volatile("ld.shared.v2.b64 {%0,%1}, [%2];" : "=l"(x), "=l"(y) : "r"(a));
}
__device__ __forceinline__ void sts128(uint32_t a, ull x, ull y) {
    asm volatile("st.shared.v2.b64 [%0], {%1,%2};" :: "r"(a), "l"(x), "l"(y) : "memory");
}
__device__ __forceinline__ void ldg128(ull& x, ull& y, const void* p) {
    asm volatile("ld.global.nc.v2.b64 {%0,%1}, [%2];" : "=l"(x), "=l"(y) : "l"(p));
}
__device__ __forceinline__ void stg128(void* p, ull x, ull y) {
    asm volatile("st.global.v2.b64 [%0], {%1,%2};" :: "l"(p), "l"(x), "l"(y) : "memory");
}

static __device__ float g_xv[PB * PN * PO];   // x_v = fea^T @ Wv + bv   [B,N,64]
static __device__ float g_a [PB * PN * PG];   // (x_k @ we_w1)*we_s + a0 [B,N,8]
static __device__ float g_c [PB * PM * PG];   // ((x_q-cpr)@we_w1)*we_s - we_b
static __device__ float g_wka[PC * PG];
static __device__ float g_wqa[PC * PG];
static __device__ float g_wca[PO * PG];
static __device__ float g_c0[PG];
static __device__ float g_a0[PG];
static __device__ float g_pw1f[3 * PO];       // pe_w1 col-scaled by pe_s
static __device__ float g_cw1f[3 * PO];       // cpe_w1 col-scaled by cpe_s

// ---------------------------------------------------------------------------
// Kernel 0: fold small weight combos
// ---------------------------------------------------------------------------
__global__ void fold_kernel(const float* __restrict__ Wq, const float* __restrict__ bq,
                            const float* __restrict__ Wk, const float* __restrict__ bk,
                            const float* __restrict__ cpe_w1, const float* __restrict__ cpe_s,
                            const float* __restrict__ cpe_w2, const float* __restrict__ cpe_b2,
                            const float* __restrict__ pe_w1, const float* __restrict__ pe_s,
                            const float* __restrict__ we_w1, const float* __restrict__ we_s,
                            const float* __restrict__ we_b) {
    int tid = threadIdx.x;             // 512 threads
    int c = tid >> 3, g = tid & 7;
    float s = we_s[g];
    float aK = 0.f, aQ = 0.f, aC = 0.f;
    #pragma unroll 8
    for (int o = 0; o < 64; o++) {
        float w1 = we_w1[o * 8 + g];
        aK = fmaf(Wk[c * 64 + o],     w1, aK);
        aQ = fmaf(Wq[c * 64 + o],     w1, aQ);
        aC = fmaf(cpe_w2[c * 64 + o], w1, aC);
    }
    g_wka[c * 8 + g] = aK * s;
    g_wqa[c * 8 + g] = aQ * s;
    g_wca[c * 8 + g] = aC * s;

    if (tid < 8) {
        float a0 = 0.f, c0 = 0.f;
        for (int o = 0; o < 64; o++) {
            float w1 = we_w1[o * 8 + tid];
            a0 = fmaf(bk[o], w1, a0);
            c0 = fmaf(bq[o] - cpe_b2[o], w1, c0);
        }
        g_a0[tid] = a0 * we_s[tid];
        g_c0[tid] = c0 * we_s[tid] - we_b[tid];
    }
    if (tid < 192) {
        int j = tid % 64;
        g_pw1f[tid] = pe_w1[tid]  * pe_s[j];
        g_cw1f[tid] = cpe_w1[tid] * cpe_s[j];
    }
}

// ---------------------------------------------------------------------------
// Kernel 1: per-point precompute with packed f32x2 accumulators.
// ---------------------------------------------------------------------------
__global__ void __launch_bounds__(256, 2)
point_kernel(const float* __restrict__ fea,
             const float* __restrict__ Wv,
             const float* __restrict__ bv) {
    __shared__ float sWv[64 * 64];
    __shared__ float sWka[64 * 8];
    __shared__ float sbv[64];
    __shared__ float sa0[8];
    int tid = threadIdx.x;
    for (int i = tid; i < 4096; i += 256) sWv[i] = Wv[i];
    for (int i = tid; i < 512; i += 256)  sWka[i] = g_wka[i];
    if (tid < 64) sbv[tid] = bv[tid];
    if (tid < 8)  sa0[tid] = g_a0[tid];
    __syncthreads();

    uint32_t aWv = (uint32_t)__cvta_generic_to_shared(sWv);
    uint32_t aKa = (uint32_t)__cvta_generic_to_shared(sWka);
    uint32_t aBv = (uint32_t)__cvta_generic_to_shared(sbv);
    uint32_t aA0 = (uint32_t)__cvta_generic_to_shared(sa0);

    int gp = blockIdx.x * 256 + tid;        // global point
    int b = gp >> 14;
    int n = gp & (PN - 1);
    const float* fp = fea + (size_t)b * PC * PN + n;

    ull acc2[32];
    ull ag2[4];
    #pragma unroll
    for (int i = 0; i < 32; i++) acc2[i] = lds64(aBv + i * 8);
    #pragma unroll
    for (int i = 0; i < 4; i++)  ag2[i]  = lds64(aA0 + i * 8);

    #pragma unroll 4
    for (int c = 0; c < 64; c++) {
        float f = fp[(size_t)c * PN];
        ull ff = pack2(f, f);
        uint32_t rowa = aWv + c * 256;
        #pragma unroll
        for (int p = 0; p < 16; p++) {
            ull w0, w1;
            lds128(w0, w1, rowa + p * 16);
            ffma2(acc2[p * 2 + 0], ff, w0, acc2[p * 2 + 0]);
            ffma2(acc2[p * 2 + 1], ff, w1, acc2[p * 2 + 1]);
        }
        ull k0, k1, k2, k3;
        lds128(k0, k1, aKa + c * 32);
        lds128(k2, k3, aKa + c * 32 + 16);
        ffma2(ag2[0], ff, k0, ag2[0]);
        ffma2(ag2[1], ff, k1, ag2[1]);
        ffma2(ag2[2], ff, k2, ag2[2]);
        ffma2(ag2[3], ff, k3, ag2[3]);
    }

    float* ov = g_xv + (size_t)gp * 64;
    #pragma unroll
    for (int p = 0; p < 16; p++)
        stg128(ov + p * 4, acc2[p * 2], acc2[p * 2 + 1]);
    float* av = g_a + (size_t)gp * 8;
    stg128(av,     ag2[0], ag2[1]);
    stg128(av + 4, ag2[2], ag2[3]);
}

// ---------------------------------------------------------------------------
// Kernel 2: per-center precompute (unchanged)
// ---------------------------------------------------------------------------
__global__ void center_kernel(const float* __restrict__ center_pos,
                              const float* __restrict__ center_fea,
                              const float* __restrict__ cpe_b) {
    __shared__ float sWqa[512];
    __shared__ float sWca[512];
    __shared__ float sw1[192];
    __shared__ float sb1[64];
    int tid = threadIdx.x;
    for (int i = tid; i < 512; i += 256) { sWqa[i] = g_wqa[i]; sWca[i] = g_wca[i]; }
    if (tid < 192) sw1[tid] = g_cw1f[tid];
    if (tid < 64)  sb1[tid] = cpe_b[tid];
    __syncthreads();

    int gid = blockIdx.x * 256 + tid;
    float px = center_pos[(size_t)gid * 3 + 0];
    float py = center_pos[(size_t)gid * 3 + 1];
    float pz = center_pos[(size_t)gid * 3 + 2];

    float acc[8];
    #pragma unroll
    for (int g = 0; g < 8; g++) acc[g] = __ldg(g_c0 + g);

    int b = gid >> 14;
    int m = gid & (PM - 1);
    const float* cf = center_fea + (size_t)b * PC * PM + m;
    #pragma unroll 4
    for (int i = 0; i < 64; i++) {
        float h = fmaxf(fmaf(px, sw1[i], fmaf(py, sw1[64 + i], fmaf(pz, sw1[128 + i], sb1[i]))), 0.f);
        float f = cf[(size_t)i * PM];
        const float4* qa = (const float4*)(sWqa + i * 8);
        const float4* ca = (const float4*)(sWca + i * 8);
        float4 q0 = qa[0], q1 = qa[1], c0 = ca[0], c1 = ca[1];
        acc[0] += f * q0.x - h * c0.x;  acc[1] += f * q0.y - h * c0.y;
        acc[2] += f * q0.z - h * c0.z;  acc[3] += f * q0.w - h * c0.w;
        acc[4] += f * q1.x - h * c1.x;  acc[5] += f * q1.y - h * c1.y;
        acc[6] += f * q1.z - h * c1.z;  acc[7] += f * q1.w - h * c1.w;
    }
    float4* cv = (float4*)(g_c + (size_t)gid * 8);
    cv[0] = make_float4(acc[0], acc[1], acc[2], acc[3]);
    cv[1] = make_float4(acc[4], acc[5], acc[6], acc[7]);
}

// ---------------------------------------------------------------------------
// Kernel 3: main attention. 128 thr/block = 8 centers x 16 threads.
// Thread t owns j-slice [t*4, t*4+4) and outputs o = t*4..t*4+3 (group t>>1).
// Softmax weights staged in smem DUPLICATED as {w,w} pairs so the edge loop's
// H accumulation runs on fma.rn.f32x2 with zero packing movs.
// ---------------------------------------------------------------------------
// smem float layout:
//   0     s_we2  [64]
//   64    s_web2 [8]
//   72    s_ik   [128] (int)
//   200   s_d    [8*16 float4] = 512 f
//   712   s_w    [8*16*16] = 2048 f   ({w,w} pairs, 16 per edge)
//   2760  s_H    [8 * 576]            (8 rows x 72, 16B-aligned rows)
//   (s_out [64*9] overlays s_H after full-block sync)
#define SM_WE2   0
#define SM_WEB2  64
#define SM_IK    72
#define SM_D     200
#define SM_W     712
#define SM_H     2760
#define SM_TOT   (2760 + 8 * 576)

__global__ void __launch_bounds__(128, 5)
attn_kernel(const float* __restrict__ center_pos,
            const float* __restrict__ pos,
            const int* __restrict__ idx,
            const float* __restrict__ pe_w2,
            const float* __restrict__ pe_b,
            const float* __restrict__ pe_b2,
            const float* __restrict__ we_w2,
            const float* __restrict__ we_b2,
            float* __restrict__ out) {
    extern __shared__ float sm[];
    float*  s_we2 = sm + SM_WE2;
    float*  s_web2= sm + SM_WEB2;
    int*    s_ik  = (int*)(sm + SM_IK);
    float4* s_d   = (float4*)(sm + SM_D);
    float4* s_w4  = (float4*)(sm + SM_W);
    float*  s_H   = sm + SM_H;

    const int tid = threadIdx.x;
    if (tid < 64) s_we2[tid] = we_w2[tid];
    if (tid < 8)  s_web2[tid] = we_b2[tid];
    __syncthreads();

    const unsigned FULL = 0xffffffffu;
    const int ci = tid >> 4;           // center within block (0..7)
    const int t  = tid & 15;           // lane within center
    const int g  = t >> 1;             // my output group
    const int gidBase = blockIdx.x * 8;
    const int gid = gidBase + ci;
    const int b = gid >> 14;

    // --- prologue: my edge (k = t) ---
    int myik;
    {
        int ik = idx[(size_t)gid * 16 + t];
        myik = b * PN + ik;
        s_ik[ci * 16 + t] = myik;
        const float* pp = pos + (size_t)myik * 3;
        float cx = center_pos[(size_t)gid * 3 + 0];
        float cy = center_pos[(size_t)gid * 3 + 1];
        float cz = center_pos[(size_t)gid * 3 + 2];
        s_d[ci * 16 + t] = make_float4(pp[0] - cx, pp[1] - cy, pp[2] - cz, 0.f);
    }

    // --- logits + softmax for my edge ---
    {
        const float4* cpv = (const float4*)(g_c + (size_t)gid * 8);
        float4 cA = cpv[0], cB = cpv[1];
        const float4* ap = (const float4*)(g_a + (size_t)myik * 8);
        float4 a0 = ap[0], a1 = ap[1];
        float h1[8];
        h1[0] = fmaxf(a0.x - cA.x, 0.f); h1[1] = fmaxf(a0.y - cA.y, 0.f);
        h1[2] = fmaxf(a0.z - cA.z, 0.f); h1[3] = fmaxf(a0.w - cA.w, 0.f);
        h1[4] = fmaxf(a1.x - cB.x, 0.f); h1[5] = fmaxf(a1.y - cB.y, 0.f);
        h1[6] = fmaxf(a1.z - cB.z, 0.f); h1[7] = fmaxf(a1.w - cB.w, 0.f);
        float lg[8];
        #pragma unroll
        for (int gg = 0; gg < 8; gg++) {
            float acc = s_web2[gg];
            #pragma unroll
            for (int gp = 0; gp < 8; gp++)
                acc = fmaf(h1[gp], s_we2[gp * 8 + gg], acc);
            lg[gg] = acc;
        }
        float mx[8];
        #pragma unroll
        for (int gg = 0; gg < 8; gg++) mx[gg] = lg[gg];
        #pragma unroll
        for (int s = 1; s < 16; s <<= 1)
            #pragma unroll
            for (int gg = 0; gg < 8; gg++)
                mx[gg] = fmaxf(mx[gg], __shfl_xor_sync(FULL, mx[gg], s, 16));
        float e[8], sum[8];
        #pragma unroll
        for (int gg = 0; gg < 8; gg++) { e[gg] = __expf(lg[gg] - mx[gg]); sum[gg] = e[gg]; }
        #pragma unroll
        for (int s = 1; s < 16; s <<= 1)
            #pragma unroll
            for (int gg = 0; gg < 8; gg++)
                sum[gg] += __shfl_xor_sync(FULL, sum[gg], s, 16);
        #pragma unroll
        for (int gg = 0; gg < 8; gg++)
            e[gg] *= __fdividef(1.f, sum[gg]);
        // duplicated {w,w} pairs: 16 floats per edge
        float4* wb = s_w4 + (ci * 16 + t) * 4;
        wb[0] = make_float4(e[0], e[0], e[1], e[1]);
        wb[1] = make_float4(e[2], e[2], e[3], e[3]);
        wb[2] = make_float4(e[4], e[4], e[5], e[5]);
        wb[3] = make_float4(e[6], e[6], e[7], e[7]);
    }
    __syncwarp();

    // --- per-thread pe_w1 slice (folded with pe_s) + bias ---
    float wxa[4], wxb[4], wxc[4], bb[4];
    #pragma unroll
    for (int jj = 0; jj < 4; jj++) {
        wxa[jj] = __ldg(g_pw1f + 0 * 64 + t * 4 + jj);
        wxb[jj] = __ldg(g_pw1f + 1 * 64 + t * 4 + jj);
        wxc[jj] = __ldg(g_pw1f + 2 * 64 + t * 4 + jj);
        bb[jj]  = __ldg(pe_b + t * 4 + jj);
    }

    // --- edge loop ---
    ull Hc2[16];           // Hc2[g*2+p] = H[g][j-pair p]
    ull onv2[2] = {0ull, 0ull};
    #pragma unroll
    for (int i = 0; i < 16; i++) Hc2[i] = 0ull;

    uint32_t aW = (uint32_t)__cvta_generic_to_shared(s_w4) + ci * 16 * 64;
    const int ekb = ci * 16;
    #pragma unroll
    for (int k = 0; k < 16; k++) {
        int ikk = s_ik[ekb + k];
        float4 d = s_d[ekb + k];
        ull wp0, wp1, wp2, wp3, wp4, wp5, wp6, wp7;
        lds128(wp0, wp1, aW + k * 64);
        lds128(wp2, wp3, aW + k * 64 + 16);
        lds128(wp4, wp5, aW + k * 64 + 32);
        lds128(wp6, wp7, aW + k * 64 + 48);
        ull wtp = lds64(aW + k * 64 + g * 8);
        ull v0, v1;
        ldg128(v0, v1, g_xv + (size_t)ikk * 64 + t * 4);

        float h0 = fmaxf(fmaf(d.x, wxa[0], fmaf(d.y, wxb[0], fmaf(d.z, wxc[0], bb[0]))), 0.f);
        float h1 = fmaxf(fmaf(d.x, wxa[1], fmaf(d.y, wxb[1], fmaf(d.z, wxc[1], bb[1]))), 0.f);
        float h2 = fmaxf(fmaf(d.x, wxa[2], fmaf(d.y, wxb[2], fmaf(d.z, wxc[2], bb[2]))), 0.f);
        float h3 = fmaxf(fmaf(d.x, wxa[3], fmaf(d.y, wxb[3], fmaf(d.z, wxc[3], bb[3]))), 0.f);
        ull h01 = pack2(h0, h1);
        ull h23 = pack2(h2, h3);

        ffma2(Hc2[0],  wp0, h01, Hc2[0]);  ffma2(Hc2[1],  wp0, h23, Hc2[1]);
        ffma2(Hc2[2],  wp1, h01, Hc2[2]);  ffma2(Hc2[3],  wp1, h23, Hc2[3]);
        ffma2(Hc2[4],  wp2, h01, Hc2[4]);  ffma2(Hc2[5],  wp2, h23, Hc2[5]);
        ffma2(Hc2[6],  wp3, h01, Hc2[6]);  ffma2(Hc2[7],  wp3, h23, Hc2[7]);
        ffma2(Hc2[8],  wp4, h01, Hc2[8]);  ffma2(Hc2[9],  wp4, h23, Hc2[9]);
        ffma2(Hc2[10], wp5, h01, Hc2[10]); ffma2(Hc2[11], wp5, h23, Hc2[11]);
        ffma2(Hc2[12], wp6, h01, Hc2[12]); ffma2(Hc2[13], wp6, h23, Hc2[13]);
        ffma2(Hc2[14], wp7, h01, Hc2[14]); ffma2(Hc2[15], wp7, h23, Hc2[15]);

        ffma2(onv2[0], wtp, v0, onv2[0]);
        ffma2(onv2[1], wtp, v1, onv2[1]);
    }

    // --- H transpose through smem (warp-local) ---
    {
        uint32_t aH = (uint32_t)__cvta_generic_to_shared(s_H) + ci * 2304 + t * 16;
        #pragma unroll
        for (int gg = 0; gg < 8; gg++)
            sts128(aH + gg * 288, Hc2[gg * 2], Hc2[gg * 2 + 1]);
    }
    __syncwarp();

    // --- final contraction: pr[o..o+3] = pe_b2 + H[g]·pe_w2[:,o..o+3] ---
    ull pr0 = pack2(__ldg(pe_b2 + t * 4 + 0), __ldg(pe_b2 + t * 4 + 1));
    ull pr1 = pack2(__ldg(pe_b2 + t * 4 + 2), __ldg(pe_b2 + t * 4 + 3));
    {
        const float* hrow = s_H + ci * 576 + g * 72;
        const float* pwb = pe_w2 + t * 4;
        #pragma unroll 4
        for (int j4 = 0; j4 < 16; j4++) {
            float4 hv = *(const float4*)(hrow + j4 * 4);
            ull p0, p1;
            ull hp;
            hp = pack2(hv.x, hv.x);
            ldg128(p0, p1, pwb + (j4 * 4 + 0) * 64);
            ffma2(pr0, hp, p0, pr0); ffma2(pr1, hp, p1, pr1);
            hp = pack2(hv.y, hv.y);
            ldg128(p0, p1, pwb + (j4 * 4 + 1) * 64);
            ffma2(pr0, hp, p0, pr0); ffma2(pr1, hp, p1, pr1);
            hp = pack2(hv.z, hv.z);
            ldg128(p0, p1, pwb + (j4 * 4 + 2) * 64);
            ffma2(pr0, hp, p0, pr0); ffma2(pr1, hp, p1, pr1);
            hp = pack2(hv.w, hv.w);
            ldg128(p0, p1, pwb + (j4 * 4 + 3) * 64);
            ffma2(pr0, hp, p0, pr0); ffma2(pr1, hp, p1, pr1);
        }
    }
    __syncthreads();   // all warps done with s_H — safe to overlay s_out

    // --- stage output [o][m_local] for coalesced [B,O,M] writes ---
    float* s_out = s_H;   // 64 x 9 overlay
    {
        float2 a0 = unpack2(onv2[0]), a1 = unpack2(onv2[1]);
        float2 b0 = unpack2(pr0),     b1 = unpack2(pr1);
        s_out[(t * 4 + 0) * 9 + ci] = a0.x + b0.x;
        s_out[(t * 4 + 1) * 9 + ci] = a0.y + b0.y;
        s_out[(t * 4 + 2) * 9 + ci] = a1.x + b1.x;
        s_out[(t * 4 + 3) * 9 + ci] = a1.y + b1.y;
    }
    __syncthreads();

    const int m0 = gidBase & (PM - 1);
    float* ob = out + (size_t)(gidBase >> 14) * PO * PM + m0;
    #pragma unroll
    for (int q = 0; q < 4; q++) {
        int lin = q * 128 + tid;
        int o = lin >> 3;
        int ml = lin & 7;
        ob[(size_t)o * PM + ml] = s_out[o * 9 + ml];
    }
}

// ---------------------------------------------------------------------------
extern "C" void kernel_launch(void* const* d_in, const int* in_sizes, int n_in,
                              void* d_out, int out_size) {
    (void)in_sizes; (void)n_in; (void)out_size;
    const float* center_pos = (const float*)d_in[0];
    const float* center_fea = (const float*)d_in[1];
    const float* pos        = (const float*)d_in[2];
    const float* fea        = (const float*)d_in[3];
    const int*   idx        = (const int*)d_in[4];
    const float* Wq  = (const float*)d_in[5];
    const float* bq  = (const float*)d_in[6];
    const float* Wk  = (const float*)d_in[7];
    const float* bk  = (const float*)d_in[8];
    const float* Wv  = (const float*)d_in[9];
    const float* bv  = (const float*)d_in[10];
    const float* cpe_w1 = (const float*)d_in[11];
    const float* cpe_s  = (const float*)d_in[12];
    const float* cpe_b  = (const float*)d_in[13];
    const float* cpe_w2 = (const float*)d_in[14];
    const float* cpe_b2 = (const float*)d_in[15];
    const float* pe_w1  = (const float*)d_in[16];
    const float* pe_s   = (const float*)d_in[17];
    const float* pe_b   = (const float*)d_in[18];
    const float* pe_w2  = (const float*)d_in[19];
    const float* pe_b2  = (const float*)d_in[20];
    const float* we_w1  = (const float*)d_in[21];
    const float* we_s   = (const float*)d_in[22];
    const float* we_b   = (const float*)d_in[23];
    const float* we_w2  = (const float*)d_in[24];
    const float* we_b2  = (const float*)d_in[25];
    float* out = (float*)d_out;

    fold_kernel<<<1, 512>>>(Wq, bq, Wk, bk, cpe_w1, cpe_s, cpe_w2, cpe_b2,
                            pe_w1, pe_s, we_w1, we_s, we_b);
    point_kernel<<<(PB * PN) / 256, 256>>>(fea, Wv, bv);
    center_kernel<<<(PB * PM) / 256, 256>>>(center_pos, center_fea, cpe_b);

    const int smem = SM_TOT * 4;   // ~29.5 KB
    cudaFuncSetAttribute(attn_kernel, cudaFuncAttributeMaxDynamicSharedMemorySize, smem);
    attn_kernel<<<(PB * PM) / 8, 128, smem>>>(center_pos, pos, idx,
                                              pe_w2, pe_b, pe_b2, we_w2, we_b2, out);
}